// round 13
// baseline (speedup 1.0000x reference)
#include <cuda_runtime.h>

// x: (2,1,128,128,128) f32; vectors: (10,12) f32
// out: (2, 768, 32, 32, 32) f32, o = ((pd*4+ph)*4+pw)*12 + v
// bin = searchsorted(HU_EDGES, x, 'right') = sum(x >= edge_i)
//
// grid = 2048 blocks (b,gd,gh), block = 512 threads (pd,ph,pw,gw4).
// Each thread: 4 scalar LDG -> 4 bins -> 12 coalesced float4 stores.
// All indices 32-bit (out = 12.58M float4s, x = 4.2M floats).

__device__ __forceinline__ int bin1(float f)
{
    return (f >= -1000.0f) + (f >= -75.0f) + (f >= 0.0f)
         + (f >= 15.0f)    + (f >= 25.0f)  + (f >= 40.0f)
         + (f >= 50.0f)    + (f >= 200.0f) + (f >= 1000.0f);
}

__global__ __launch_bounds__(512, 3) void lcv_kernel(
    const float* __restrict__ x,
    const float* __restrict__ vectors,
    float* __restrict__ out)
{
    __shared__ float vs[120];          // 10 bins x 12 dims
    const int tid = threadIdx.x;
    if (tid < 120) vs[tid] = vectors[tid];
    __syncthreads();

    const int gw4 = tid & 7;
    const int pw  = (tid >> 3) & 3;
    const int ph  = (tid >> 5) & 3;
    const int pd  = tid >> 7;

    const int bi = blockIdx.x;
    const int gh = bi & 31;
    const int gd = (bi >> 5) & 31;
    const int b  = bi >> 10;

    // voxels this thread needs: w = gw4*16 + 4k + pw, k = 0..3
    const int xoff = (((b * 128 + (gd * 4 + pd)) * 128
                      + (gh * 4 + ph)) * 128) + gw4 * 16 + pw;
    const float* xr = x + xoff;
    const float* p0 = vs + bin1(__ldg(xr + 0))  * 12;
    const float* p1 = vs + bin1(__ldg(xr + 4))  * 12;
    const float* p2 = vs + bin1(__ldg(xr + 8))  * 12;
    const float* p3 = vs + bin1(__ldg(xr + 12)) * 12;

    float4* out4 = reinterpret_cast<float4*>(out);
    const int p = (pd * 4 + ph) * 4 + pw;
    // float4-unit offset; max = 2*768*8192 = 12.58M, fits in int
    const int obase = (b * 768 + p * 12) * 8192 + (gd * 32 + gh) * 8 + gw4;

    #pragma unroll
    for (int v = 0; v < 12; v++) {
        float4 r;
        r.x = p0[v]; r.y = p1[v]; r.z = p2[v]; r.w = p3[v];
        __stcs(&out4[obase + v * 8192], r);
    }
}

extern "C" void kernel_launch(void* const* d_in, const int* in_sizes, int n_in,
                              void* d_out, int out_size)
{
    const float* x       = (const float*)d_in[0];
    const float* vectors = (const float*)d_in[1];
    float* out           = (float*)d_out;
    lcv_kernel<<<2048, 512>>>(x, vectors, out);
}

// round 14
// speedup vs baseline: 1.0401x; 1.0401x over previous
#include <cuda_runtime.h>

// x: (2,1,128,128,128) f32; vectors: (10,12) f32
// out: (2, 768, 32, 32, 32) f32, o = ((pd*4+ph)*4+pw)*12 + v
// bin = searchsorted(HU_EDGES, x, 'right') = sum(x >= edge_i)
//
// grid = 2048 blocks (b,gd,gh), block = 512 threads.
// Phase 1: 1 coalesced LDG.128/thread -> 4 bins packed -> smem (512 words).
// Phase 2: 1 LDS.128 (4 bins) + 12 LDS.128 table rows -> 12 transposed
//          float4 streaming stores.

__global__ __launch_bounds__(512, 3) void lcv_kernel(
    const float* __restrict__ x,
    const float* __restrict__ vectors,
    float* __restrict__ out)
{
    __shared__ float4 vtab[30];           // 10 bins x 12 dims, float4 rows
    __shared__ unsigned int sbin[512];    // [pd][ph][wq]: 4 bins per word

    const int tid = threadIdx.x;
    if (tid < 120) reinterpret_cast<float*>(vtab)[tid] = vectors[tid];

    const int bi = blockIdx.x;
    const int gh = bi & 31;
    const int gd = (bi >> 5) & 31;
    const int b  = bi >> 10;

    // ---- Phase 1: one packed-bin word per thread (coalesced float4 load)
    {
        const int wq  = tid & 31;          // float4 index along w
        const int ph1 = (tid >> 5) & 3;
        const int pd1 = tid >> 7;
        const int xoff = ((b * 128 + gd * 4 + pd1) * 128
                          + gh * 4 + ph1) * 128 + wq * 4;
        float4 xv = *reinterpret_cast<const float4*>(x + xoff);
        const float* xp = &xv.x;
        unsigned int packed = 0;
        #pragma unroll
        for (int q = 0; q < 4; q++) {
            float f = xp[q];
            unsigned int bn =
                  (f >= -1000.0f) + (f >= -75.0f) + (f >= 0.0f)
                + (f >= 15.0f)    + (f >= 25.0f)  + (f >= 40.0f)
                + (f >= 50.0f)    + (f >= 200.0f) + (f >= 1000.0f);
            packed |= bn << (q * 8);
        }
        sbin[tid] = packed;
    }
    __syncthreads();

    // ---- Phase 2: 12 output float4s per thread
    const int gw4 = tid & 7;
    const int pw  = (tid >> 3) & 3;
    const int ph  = (tid >> 5) & 3;
    const int pd  = tid >> 7;

    // bins of voxels w = gw4*16 + 4k + pw, k = 0..3 (byte pw of 4 words)
    const uint4 wv = reinterpret_cast<const uint4*>(sbin)[(pd * 4 + ph) * 8 + gw4];
    const int sh = pw * 8;
    const int b0 = ((wv.x >> sh) & 0xFF) * 3;
    const int b1 = ((wv.y >> sh) & 0xFF) * 3;
    const int b2 = ((wv.z >> sh) & 0xFF) * 3;
    const int b3 = ((wv.w >> sh) & 0xFF) * 3;

    float4* out4 = reinterpret_cast<float4*>(out);
    const int p = (pd * 4 + ph) * 4 + pw;
    const int obase = (b * 768 + p * 12) * 8192 + (gd * 32 + gh) * 8 + gw4;

    #pragma unroll
    for (int c = 0; c < 3; c++) {
        float4 t0 = vtab[b0 + c];
        float4 t1 = vtab[b1 + c];
        float4 t2 = vtab[b2 + c];
        float4 t3 = vtab[b3 + c];
        __stcs(&out4[obase + (4 * c + 0) * 8192], make_float4(t0.x, t1.x, t2.x, t3.x));
        __stcs(&out4[obase + (4 * c + 1) * 8192], make_float4(t0.y, t1.y, t2.y, t3.y));
        __stcs(&out4[obase + (4 * c + 2) * 8192], make_float4(t0.z, t1.z, t2.z, t3.z));
        __stcs(&out4[obase + (4 * c + 3) * 8192], make_float4(t0.w, t1.w, t2.w, t3.w));
    }
}

extern "C" void kernel_launch(void* const* d_in, const int* in_sizes, int n_in,
                              void* d_out, int out_size)
{
    const float* x       = (const float*)d_in[0];
    const float* vectors = (const float*)d_in[1];
    float* out           = (float*)d_out;
    lcv_kernel<<<2048, 512>>>(x, vectors, out);
}